// round 17
// baseline (speedup 1.0000x reference)
#include <cuda_runtime.h>
#include <cuda_fp16.h>
#include <cstddef>

// BilinearMixture: out[e,c] = sum_w (sum_d u[ui,d]*W[w,d]*v[vi,d]) * scalars[w,c]
//                           + u_bias[ui,c] + v_bias[vi,c]
// E=2e6, D=128, NUM_W=3, C=5.
//
// Phase 1: convert u/v tables + W to fp16 scratch (51 MB -> L2-resident).
// Phase 2: 8 lanes/edge, 4 groups, ONE edge per thread (4 edges/warp).
//   R16 math (fp16 hfma2 chains, single flush, hoisted bias) at half the
//   register footprint: ~48 regs -> 5 CTAs/SM (40 warps, occ ~63% vs 42%).
//   Trades +8% wavefronts/edge (W, idx) for +56% latency-hiding warps on a
//   76%-busy L1 pipe.

#define D 128
#define NUM_W 3
#define NUM_C 5
#define NUM_USERS 100000
#define NUM_ITEMS 100000
#define THREADS 256
#define WARPS_PER_BLOCK (THREADS / 32)
#define EDGES_PER_WARP 4
#define EDGES_PER_BLOCK (WARPS_PER_BLOCK * EDGES_PER_WARP)  // 32

#define ROW_U4 (D / 8)            // 16 uint4 per 128-half row
__device__ uint4 g_u16[(size_t)NUM_USERS * ROW_U4];
__device__ uint4 g_v16[(size_t)NUM_ITEMS * ROW_U4];
__device__ uint4 g_w16[NUM_W * ROW_U4];     // 48 uint4

// ---------------- conversion kernel: fp32 -> fp16 ----------------
__global__ __launch_bounds__(256)
void convert_kernel(const float4* __restrict__ u_src,
                    const float4* __restrict__ v_src,
                    const float4* __restrict__ w_src,
                    int n_u, int n_v, int n_w)   // uint4 counts
{
    const int total = n_u + n_v + n_w;
    for (int idx = blockIdx.x * blockDim.x + threadIdx.x; idx < total;
         idx += gridDim.x * blockDim.x)
    {
        const float4* s;
        uint4* dst;
        int j;
        if (idx < n_u)              { s = u_src; dst = g_u16; j = idx; }
        else if (idx < n_u + n_v)   { s = v_src; dst = g_v16; j = idx - n_u; }
        else                        { s = w_src; dst = g_w16; j = idx - n_u - n_v; }
        const float4 a = s[2 * j];
        const float4 b = s[2 * j + 1];
        __half2 h0 = __floats2half2_rn(a.x, a.y);
        __half2 h1 = __floats2half2_rn(a.z, a.w);
        __half2 h2 = __floats2half2_rn(b.x, b.y);
        __half2 h3 = __floats2half2_rn(b.z, b.w);
        uint4 o;
        o.x = *reinterpret_cast<unsigned*>(&h0);
        o.y = *reinterpret_cast<unsigned*>(&h1);
        o.z = *reinterpret_cast<unsigned*>(&h2);
        o.w = *reinterpret_cast<unsigned*>(&h3);
        dst[j] = o;
    }
}

// ---------------- main kernel ----------------
template <bool GUARD>
__global__ __launch_bounds__(THREADS, 5)
void bilinear_mixture_kernel(
    const int*   __restrict__ u_idx,
    const int*   __restrict__ v_idx,
    const float* __restrict__ scalars,
    const float* __restrict__ u_bias,
    const float* __restrict__ v_bias,
    float*       __restrict__ out,
    int E)
{
    const int tid  = threadIdx.x;
    const int lane = tid & 31;
    const int l    = lane & 7;        // lane within edge-group (0..7)
    const int g    = lane >> 3;       // edge-group within warp (0..3)
    const int warp = tid >> 5;

    const int e = blockIdx.x * EDGES_PER_BLOCK + warp * EDGES_PER_WARP + g;
    bool valid = true;
    if (GUARD) valid = (e < E);

    const int ui = valid ? u_idx[e] : 0;
    const int vi = valid ? v_idx[e] : 0;

    // 4 feature loads issued up front (MLP 4/lane, 4 wf/edge warp-wide).
    uint4 ua[2], va[2];
#pragma unroll
    for (int i = 0; i < 2; i++) {
        ua[i] = g_u16[(size_t)ui * ROW_U4 + i * 8 + l];
        va[i] = g_v16[(size_t)vi * ROW_U4 + i * 8 + l];
    }

    // Bias gathers issued now; latency hides under the compute loop.
    float ub = 0.f, vb = 0.f;
    if (l < NUM_C) {
        ub = __ldg(u_bias + (size_t)ui * NUM_C + l);
        vb = __ldg(v_bias + (size_t)vi * NUM_C + l);
    }

    // fp16 accumulators carried across both i-iterations (8-term chains).
    __half2 hA0, hA1, hA2;
    {
        const __half2 z = __float2half2_rn(0.f);
        hA0 = z; hA1 = z; hA2 = z;
    }

#pragma unroll
    for (int i = 0; i < 2; i++) {
        // W fp16 broadcast loads (1 wf each); stay in fp16.
        const uint4 w0 = g_w16[0 * ROW_U4 + i * 8 + l];
        const uint4 w1 = g_w16[1 * ROW_U4 + i * 8 + l];
        const uint4 w2 = g_w16[2 * ROW_U4 + i * 8 + l];
        const __half2* w0h = reinterpret_cast<const __half2*>(&w0);
        const __half2* w1h = reinterpret_cast<const __half2*>(&w1);
        const __half2* w2h = reinterpret_cast<const __half2*>(&w2);
        const __half2* uah = reinterpret_cast<const __half2*>(&ua[i]);
        const __half2* vah = reinterpret_cast<const __half2*>(&va[i]);

#pragma unroll
        for (int k = 0; k < 4; k++) {
            const __half2 pa = __hmul2(uah[k], vah[k]);
            hA0 = __hfma2(pa, w0h[k], hA0);
            hA1 = __hfma2(pa, w1h[k], hA1);
            hA2 = __hfma2(pa, w2h[k], hA2);
        }
    }

    // Single flush to fp32.
    float a0, a1, a2;
    {
        float2 t;
        t = __half22float2(hA0); a0 = t.x + t.y;
        t = __half22float2(hA1); a1 = t.x + t.y;
        t = __half22float2(hA2); a2 = t.x + t.y;
    }

    // Per-class mix constants (L1-hit broadcast; cheap in the tail).
    float s0 = 0.f, s1 = 0.f, s2 = 0.f;
    if (l < NUM_C) {
        s0 = __ldg(scalars + 0 * NUM_C + l);
        s1 = __ldg(scalars + 1 * NUM_C + l);
        s2 = __ldg(scalars + 2 * NUM_C + l);
    }

    // Butterfly over the 8-lane group: 3 rounds x 3 values (fp32).
#pragma unroll
    for (int off = 4; off; off >>= 1) {
        a0 += __shfl_xor_sync(0xffffffffu, a0, off);
        a1 += __shfl_xor_sync(0xffffffffu, a1, off);
        a2 += __shfl_xor_sync(0xffffffffu, a2, off);
    }

    if (l < NUM_C && (!GUARD || valid)) {
        float o = fmaf(a0, s0, fmaf(a1, s1, a2 * s2));
        __stcs(out + (size_t)e * NUM_C + l, o + ub + vb);
    }
}

extern "C" void kernel_launch(void* const* d_in, const int* in_sizes, int n_in,
                              void* d_out, int out_size)
{
    const float* u_feats = (const float*)d_in[0];
    const float* v_feats = (const float*)d_in[1];
    const int*   u_idx   = (const int*)  d_in[2];
    const int*   v_idx   = (const int*)  d_in[3];
    const float* W       = (const float*)d_in[4];
    const float* scalars = (const float*)d_in[5];
    const float* u_bias  = (const float*)d_in[6];
    const float* v_bias  = (const float*)d_in[7];
    float* out = (float*)d_out;

    int E = in_sizes[2];  // u_idx element count

    // Phase 1: convert feature tables + W to fp16 scratch.
    const int n_u = NUM_USERS * ROW_U4;
    const int n_v = NUM_ITEMS * ROW_U4;
    const int n_w = NUM_W * ROW_U4;
    convert_kernel<<<1184, 256>>>(
        reinterpret_cast<const float4*>(u_feats),
        reinterpret_cast<const float4*>(v_feats),
        reinterpret_cast<const float4*>(W),
        n_u, n_v, n_w);

    // Phase 2: main gather kernel (guard-free when E divides evenly).
    int blocks = (E + EDGES_PER_BLOCK - 1) / EDGES_PER_BLOCK;
    if (E % EDGES_PER_BLOCK == 0) {
        bilinear_mixture_kernel<false><<<blocks, THREADS>>>(
            u_idx, v_idx, scalars, u_bias, v_bias, out, E);
    } else {
        bilinear_mixture_kernel<true><<<blocks, THREADS>>>(
            u_idx, v_idx, scalars, u_bias, v_bias, out, E);
    }
}